// round 1
// baseline (speedup 1.0000x reference)
#include <cuda_runtime.h>
#include <float.h>

// Problem constants (from reference): N=262144 rows, 80 classes, ratio=0.5.
// K = N/2 = 131072 rows actually scanned. Derived at launch from in_sizes.
#define CONF_THRESH 0.25f
#define MAX_K 131072

// Scratch (no cudaMalloc allowed): per-row max scores + global cutoff index.
__device__ float g_scores[MAX_K];
__device__ int   g_cutoff;

// ---------------------------------------------------------------------------
// Kernel 0: reset state for this graph replay.
// ---------------------------------------------------------------------------
__global__ void init_kernel(float* __restrict__ d_out) {
    g_cutoff = 0x7fffffff;
    d_out[0] = 0.0f;
}

// ---------------------------------------------------------------------------
// Kernel 1: one warp per row. Row = 80 f32 = 320 B = 20 float4 (64B-aligned).
// Lanes 0..19 each load one float4; warp-wide fmax reduction; lane 0 commits.
// ---------------------------------------------------------------------------
__global__ void __launch_bounds__(256, 8)
score_kernel(const float* __restrict__ post, int K) {
    const int warp = (blockIdx.x * blockDim.x + threadIdx.x) >> 5;
    const int lane = threadIdx.x & 31;
    if (warp >= K) return;

    const float4* row = reinterpret_cast<const float4*>(post + (size_t)warp * 80);

    float m = -FLT_MAX;
    if (lane < 20) {
        float4 v = __ldg(row + lane);
        m = fmaxf(fmaxf(v.x, v.y), fmaxf(v.z, v.w));
    }
    #pragma unroll
    for (int o = 16; o > 0; o >>= 1)
        m = fmaxf(m, __shfl_xor_sync(0xffffffffu, m, o));

    if (lane == 0) {
        g_scores[warp] = m;
        if (m < CONF_THRESH) atomicMin(&g_cutoff, warp);  // essentially never taken
    }
}

// ---------------------------------------------------------------------------
// Kernel 2: sum g_scores[i] for i < min(g_cutoff, K). Scores are L2-resident
// (just written), so this is ~512 KB of L2 traffic.
// ---------------------------------------------------------------------------
__global__ void __launch_bounds__(256)
reduce_kernel(float* __restrict__ d_out, int K) {
    const int cutoff = g_cutoff;
    const int limit  = cutoff < K ? cutoff : K;

    float s = 0.0f;
    for (int i = blockIdx.x * blockDim.x + threadIdx.x; i < limit;
         i += gridDim.x * blockDim.x)
        s += g_scores[i];

    // warp reduce
    #pragma unroll
    for (int o = 16; o > 0; o >>= 1)
        s += __shfl_xor_sync(0xffffffffu, s, o);

    // block reduce via shared
    __shared__ float warp_sums[8];
    const int wid  = threadIdx.x >> 5;
    const int lane = threadIdx.x & 31;
    if (lane == 0) warp_sums[wid] = s;
    __syncthreads();
    if (wid == 0) {
        s = (lane < (blockDim.x >> 5)) ? warp_sums[lane] : 0.0f;
        #pragma unroll
        for (int o = 4; o > 0; o >>= 1)
            s += __shfl_xor_sync(0xffffffffu, s, o);
        if (lane == 0) atomicAdd(d_out, s);
    }
}

// ---------------------------------------------------------------------------
extern "C" void kernel_launch(void* const* d_in, const int* in_sizes, int n_in,
                              void* d_out, int out_size) {
    const float* post = (const float*)d_in[0];
    // d_in[1] (pre_post_boxes) is unused by the reference's output path.
    float* out = (float*)d_out;

    const int n_rows = in_sizes[0] / 80;   // 262144
    const int K      = n_rows / 2;         // ratio = 0.5 -> 131072

    init_kernel<<<1, 1>>>(out);

    // warp per row: K warps = K*32 threads, 256 threads/block (8 warps)
    const int blocks = (K * 32 + 255) / 256;
    score_kernel<<<blocks, 256>>>(post, K);

    reduce_kernel<<<256, 256>>>(out, K);
}

// round 2
// speedup vs baseline: 1.1670x; 1.1670x over previous
#include <cuda_runtime.h>
#include <float.h>
#include <limits.h>

#define CONF_THRESH   0.25f
#define MAX_K         131072
#define ROWS_PER_WARP 8
#define THREADS       512
#define WARPS         (THREADS / 32)

// Scratch (__device__ globals; no cudaMalloc allowed).
__device__ float g_scores[MAX_K];
__device__ float g_partials[4096];
__device__ int   g_blockmin[4096];
__device__ unsigned int g_counter = 0;   // modulo-ticket: never needs reset

__global__ void __launch_bounds__(THREADS)
fused_kernel(const float* __restrict__ post, float* __restrict__ out, int K) {
    const int lane = threadIdx.x & 31;
    const int wid  = threadIdx.x >> 5;
    const int gw   = blockIdx.x * WARPS + wid;
    const int base = gw * ROWS_PER_WARP;

    const float4* p = reinterpret_cast<const float4*>(post);

    // ---- load 8 rows per warp: lanes 0..19 each grab one float4 per row ----
    float m[ROWS_PER_WARP];
    #pragma unroll
    for (int i = 0; i < ROWS_PER_WARP; i++) {
        m[i] = -FLT_MAX;
        if (lane < 20 && base + i < K) {
            float4 v = __ldg(&p[(size_t)(base + i) * 20 + lane]);
            m[i] = fmaxf(fmaxf(v.x, v.y), fmaxf(v.z, v.w));
        }
    }

    // ---- per-row warp max reduce ----
    #pragma unroll
    for (int i = 0; i < ROWS_PER_WARP; i++) {
        #pragma unroll
        for (int o = 16; o > 0; o >>= 1)
            m[i] = fmaxf(m[i], __shfl_xor_sync(0xffffffffu, m[i], o));
    }

    // ---- warp-local sum + below-threshold min index ----
    float wsum = 0.0f;
    int   wmin = INT_MAX;
    #pragma unroll
    for (int i = 0; i < ROWS_PER_WARP; i++) {
        if (base + i < K) {
            wsum += m[i];
            if (m[i] < CONF_THRESH) wmin = min(wmin, base + i);
        }
    }

    // ---- persist row scores (for the rare fixup path) ----
    if (lane == 0) {
        if (base + ROWS_PER_WARP <= K) {
            float4 a = make_float4(m[0], m[1], m[2], m[3]);
            float4 b = make_float4(m[4], m[5], m[6], m[7]);
            reinterpret_cast<float4*>(g_scores + base)[0] = a;
            reinterpret_cast<float4*>(g_scores + base)[1] = b;
        } else {
            for (int i = 0; i < ROWS_PER_WARP; i++)
                if (base + i < K) g_scores[base + i] = m[i];
        }
    }

    // ---- block reduce ----
    __shared__ float sWs[WARPS];
    __shared__ int   sWm[WARPS];
    __shared__ int   sLast;
    if (lane == 0) { sWs[wid] = wsum; sWm[wid] = wmin; }
    __syncthreads();

    if (threadIdx.x < 32) {
        float s  = (lane < WARPS) ? sWs[lane] : 0.0f;
        int   mn = (lane < WARPS) ? sWm[lane] : INT_MAX;
        #pragma unroll
        for (int o = 16; o > 0; o >>= 1) {
            s  += __shfl_xor_sync(0xffffffffu, s, o);
            mn  = min(mn, __shfl_xor_sync(0xffffffffu, mn, o));
        }
        if (lane == 0) {
            g_partials[blockIdx.x] = s;
            g_blockmin[blockIdx.x] = mn;
            __threadfence();
            unsigned int t = atomicAdd(&g_counter, 1u);
            sLast = ((t % gridDim.x) == gridDim.x - 1) ? 1 : 0;
        }
    }
    __syncthreads();
    if (!sLast) return;

    // ================= elected last block: final reduce =================
    float s  = 0.0f;
    int   mn = INT_MAX;
    for (int i = threadIdx.x; i < gridDim.x; i += THREADS) {
        s  += g_partials[i];
        mn  = min(mn, g_blockmin[i]);
    }
    #pragma unroll
    for (int o = 16; o > 0; o >>= 1) {
        s  += __shfl_xor_sync(0xffffffffu, s, o);
        mn  = min(mn, __shfl_xor_sync(0xffffffffu, mn, o));
    }
    __shared__ float sWs2[WARPS];
    __shared__ int   sWm2[WARPS];
    __shared__ int   sCut;
    if (lane == 0) { sWs2[wid] = s; sWm2[wid] = mn; }
    __syncthreads();
    if (threadIdx.x < 32) {
        float s2  = (lane < WARPS) ? sWs2[lane] : 0.0f;
        int   mn2 = (lane < WARPS) ? sWm2[lane] : INT_MAX;
        #pragma unroll
        for (int o = 16; o > 0; o >>= 1) {
            s2  += __shfl_xor_sync(0xffffffffu, s2, o);
            mn2  = min(mn2, __shfl_xor_sync(0xffffffffu, mn2, o));
        }
        if (lane == 0) {
            int cutoff = min(mn2, K);
            sCut = cutoff;
            if (cutoff >= K) out[0] = s2;   // common path: full prefix valid
        }
    }
    __syncthreads();

    // Rare fixup: some row fell below threshold -> sum only scores[0..cutoff)
    int cutoff = sCut;
    if (cutoff < K) {
        float fs = 0.0f;
        for (int i = threadIdx.x; i < cutoff; i += THREADS)
            fs += g_scores[i];
        #pragma unroll
        for (int o = 16; o > 0; o >>= 1)
            fs += __shfl_xor_sync(0xffffffffu, fs, o);
        if (lane == 0) sWs2[wid] = fs;
        __syncthreads();
        if (threadIdx.x < 32) {
            float f2 = (lane < WARPS) ? sWs2[lane] : 0.0f;
            #pragma unroll
            for (int o = 16; o > 0; o >>= 1)
                f2 += __shfl_xor_sync(0xffffffffu, f2, o);
            if (lane == 0) out[0] = f2;
        }
    }
}

extern "C" void kernel_launch(void* const* d_in, const int* in_sizes, int n_in,
                              void* d_out, int out_size) {
    const float* post = (const float*)d_in[0];
    float* out = (float*)d_out;

    const int n_rows = in_sizes[0] / 80;   // 262144
    const int K      = n_rows / 2;         // ratio = 0.5 -> 131072

    const int rows_per_block = WARPS * ROWS_PER_WARP;          // 128
    const int blocks = (K + rows_per_block - 1) / rows_per_block;  // 1024

    fused_kernel<<<blocks, THREADS>>>(post, out, K);
}

// round 6
// speedup vs baseline: 1.3610x; 1.1662x over previous
#include <cuda_runtime.h>
#include <cstdint>
#include <float.h>
#include <limits.h>

#define CONF_THRESH   0.25f
#define ROWS_PER_TILE 128
#define TILE_FLOATS   (ROWS_PER_TILE * 80)      // 10240 floats = 2560 float4
#define HALF_F4       1280                      // float4s per 64-row half
#define THREADS       256
#define WARPS         (THREADS / 32)

// Scratch (__device__ globals; no cudaMalloc allowed).
__device__ float        g_partials[4096];
__device__ int          g_blockmin[4096];
__device__ unsigned int g_counter = 0;          // modulo ticket: no reset needed

__device__ __forceinline__ uint32_t smem_u32(const void* p) {
    uint32_t a;
    asm("{ .reg .u64 t; cvta.to.shared.u64 t, %1; cvt.u32.u64 %0, t; }"
        : "=r"(a) : "l"(p));
    return a;
}

__global__ void __launch_bounds__(THREADS)
fused_kernel(const float* __restrict__ post, float* __restrict__ out, int K) {
    __shared__ alignas(16) float tile[TILE_FLOATS];
    __shared__ int   sLast;
    __shared__ float sWs[WARPS];
    __shared__ int   sWm[WARPS];

    const int tid  = threadIdx.x;
    const int lane = tid & 31;
    const int wid  = tid >> 5;

    // ---- stage tile via cp.async.cg: 10 x 16B per thread, 2 commit groups ----
    const float4* gsrc = reinterpret_cast<const float4*>(post) +
                         (size_t)blockIdx.x * (TILE_FLOATS / 4);
    const uint32_t sbase = smem_u32(tile);

    #pragma unroll
    for (int k = 0; k < 5; k++) {               // half 0: rows 0..63
        const int idx = tid + k * THREADS;
        asm volatile("cp.async.cg.shared.global [%0], [%1], 16;"
                     :: "r"(sbase + idx * 16), "l"(gsrc + idx) : "memory");
    }
    asm volatile("cp.async.commit_group;" ::: "memory");
    #pragma unroll
    for (int k = 0; k < 5; k++) {               // half 1: rows 64..127
        const int idx = HALF_F4 + tid + k * THREADS;
        asm volatile("cp.async.cg.shared.global [%0], [%1], 16;"
                     :: "r"(sbase + idx * 16), "l"(gsrc + idx) : "memory");
    }
    asm volatile("cp.async.commit_group;" ::: "memory");

    // ---- row maxes from smem: 4 threads per row, 5 LDS.128 each ----
    const int sub = tid & 3;          // quarter within row
    const int r0  = tid >> 2;         // 0..63
    float wsum = 0.0f;
    int   wmin = INT_MAX;

    #pragma unroll
    for (int j = 0; j < 2; j++) {
        if (j == 0) asm volatile("cp.async.wait_group 1;" ::: "memory");
        else        asm volatile("cp.async.wait_group 0;" ::: "memory");
        __syncthreads();              // make staged half visible block-wide

        const int row  = j * 64 + r0;
        const int grow = blockIdx.x * ROWS_PER_TILE + row;
        const float4* rp = reinterpret_cast<const float4*>(tile + row * 80) + sub * 5;
        float m = -FLT_MAX;
        #pragma unroll
        for (int i = 0; i < 5; i++) {
            float4 v = rp[i];
            m = fmaxf(m, fmaxf(fmaxf(v.x, v.y), fmaxf(v.z, v.w)));
        }
        m = fmaxf(m, __shfl_xor_sync(0xffffffffu, m, 1));
        m = fmaxf(m, __shfl_xor_sync(0xffffffffu, m, 2));
        if (sub == 0 && grow < K) {
            wsum += m;
            if (m < CONF_THRESH) wmin = min(wmin, grow);
        }
    }

    // ---- warp reduce ----
    #pragma unroll
    for (int o = 16; o > 0; o >>= 1) {
        wsum += __shfl_xor_sync(0xffffffffu, wsum, o);
        wmin  = min(wmin, __shfl_xor_sync(0xffffffffu, wmin, o));
    }
    if (lane == 0) { sWs[wid] = wsum; sWm[wid] = wmin; }
    __syncthreads();

    // ---- block reduce + ticket ----
    if (tid < 32) {
        float s  = (lane < WARPS) ? sWs[lane] : 0.0f;
        int   mn = (lane < WARPS) ? sWm[lane] : INT_MAX;
        #pragma unroll
        for (int o = 4; o > 0; o >>= 1) {
            s  += __shfl_xor_sync(0xffffffffu, s, o);
            mn  = min(mn, __shfl_xor_sync(0xffffffffu, mn, o));
        }
        if (lane == 0) {
            g_partials[blockIdx.x] = s;
            g_blockmin[blockIdx.x] = mn;
            __threadfence();
            unsigned int t = atomicAdd(&g_counter, 1u);
            sLast = ((t % gridDim.x) == gridDim.x - 1) ? 1 : 0;
        }
    }
    __syncthreads();
    if (!sLast) return;

    // ================= elected last block: final reduce =================
    float s  = 0.0f;
    int   mn = INT_MAX;
    for (int i = tid; i < gridDim.x; i += THREADS) {
        s  += g_partials[i];
        mn  = min(mn, g_blockmin[i]);
    }
    #pragma unroll
    for (int o = 16; o > 0; o >>= 1) {
        s  += __shfl_xor_sync(0xffffffffu, s, o);
        mn  = min(mn, __shfl_xor_sync(0xffffffffu, mn, o));
    }
    __shared__ float fWs[WARPS];
    __shared__ int   fWm[WARPS];
    __shared__ int   sCut;
    if (lane == 0) { fWs[wid] = s; fWm[wid] = mn; }
    __syncthreads();
    if (tid < 32) {
        float s2  = (lane < WARPS) ? fWs[lane] : 0.0f;
        int   mn2 = (lane < WARPS) ? fWm[lane] : INT_MAX;
        #pragma unroll
        for (int o = 4; o > 0; o >>= 1) {
            s2  += __shfl_xor_sync(0xffffffffu, s2, o);
            mn2  = min(mn2, __shfl_xor_sync(0xffffffffu, mn2, o));
        }
        if (lane == 0) {
            int cutoff = min(mn2, K);
            sCut = cutoff;
            if (cutoff >= K) out[0] = s2;   // common path
        }
    }
    __syncthreads();

    // ---- rare fixup (P ~ 0.25^80): recompute prefix [0, cutoff) from gmem ----
    const int cutoff = sCut;
    if (cutoff < K) {
        float fs = 0.0f;
        for (int r = tid; r < cutoff; r += THREADS) {
            const float4* rp = reinterpret_cast<const float4*>(post + (size_t)r * 80);
            float m = -FLT_MAX;
            #pragma unroll
            for (int i = 0; i < 20; i++) {
                float4 v = __ldg(rp + i);
                m = fmaxf(m, fmaxf(fmaxf(v.x, v.y), fmaxf(v.z, v.w)));
            }
            fs += m;
        }
        #pragma unroll
        for (int o = 16; o > 0; o >>= 1)
            fs += __shfl_xor_sync(0xffffffffu, fs, o);
        if (lane == 0) fWs[wid] = fs;
        __syncthreads();
        if (tid < 32) {
            float f2 = (lane < WARPS) ? fWs[lane] : 0.0f;
            #pragma unroll
            for (int o = 4; o > 0; o >>= 1)
                f2 += __shfl_xor_sync(0xffffffffu, f2, o);
            if (lane == 0) out[0] = f2;
        }
    }
}

extern "C" void kernel_launch(void* const* d_in, const int* in_sizes, int n_in,
                              void* d_out, int out_size) {
    const float* post = (const float*)d_in[0];
    float* out = (float*)d_out;

    const int n_rows = in_sizes[0] / 80;   // 262144
    const int K      = n_rows / 2;         // ratio = 0.5 -> 131072

    const int blocks = (K + ROWS_PER_TILE - 1) / ROWS_PER_TILE;  // 1024
    fused_kernel<<<blocks, THREADS>>>(post, out, K);
}